// round 12
// baseline (speedup 1.0000x reference)
#include <cuda_runtime.h>
#include <cuda_bf16.h>
#include <cstdint>

// Problem constants (fixed by reference setup_inputs)
#define BB 8
#define SS 2048
#define HH 1024
#define NTOK (BB * SS)                 // 16384
#define BSS ((long long)BB * SS * SS)  // 33,554,432

#define PROD_BLOCKS (NTOK / 8)         // 2048 producer blocks
#define PROD_PER_BATCH 256             // producer blocks per batch

// Scratch: per-token combined scores. Non-candidates encoded as -1e30 so that
// pair_score = sS + sE + bm is guaranteed <= 0 -> invalid -> outputs 0.
__device__ float g_sS[NTOK];
__device__ float g_sE[NTOK];
__device__ int   g_ready[BB];          // per-batch producer completion count

__device__ __forceinline__ int ld_acquire(const int* p) {
    int v;
    asm volatile("ld.global.acquire.gpu.b32 %0, [%1];" : "=r"(v) : "l"(p));
    return v;
}

// ---------------------------------------------------------------------------
// Fused kernel. bid < PROD_BLOCKS: compute 8 token scores (R3 form: one warp
// per token, SoA weights in smem -> conflict-free LDS.128), then release the
// per-batch flag. ALL blocks: acquire-wait on their batch's flag, then write
// their pair tile (R1 form: 4 el/thread, plain float4 stores, monolithic grid).
// ---------------------------------------------------------------------------
__global__ __launch_bounds__(256) void fused_kernel(
    const float* __restrict__ rep,   // (B,S,H)
    const int*   __restrict__ mask,  // (B,S)
    const float* __restrict__ Ws,    // (H,2)
    const float* __restrict__ bs,    // (2,)
    const float* __restrict__ We,    // (H,2)
    const float* __restrict__ be,    // (2,)
    const float* __restrict__ Wm,    // (4,1)
    const float* __restrict__ bm,    // (1,)
    float* __restrict__ out_valid,
    float* __restrict__ out_score)
{
    __shared__ float s_w0[HH];
    __shared__ float s_w1[HH];
    __shared__ float s_w2[HH];
    __shared__ float s_w3[HH];

    const int bid = blockIdx.x;

    // ---------------- producer part ----------------
    if (bid < PROD_BLOCKS) {
        for (int h = threadIdx.x; h < HH; h += blockDim.x) {
            s_w0[h] = Ws[2 * h];
            s_w1[h] = Ws[2 * h + 1];
            s_w2[h] = We[2 * h];
            s_w3[h] = We[2 * h + 1];
        }
        __syncthreads();

        const int warp = threadIdx.x >> 5;
        const int lane = threadIdx.x & 31;
        const int t = bid * 8 + warp;

        const float4* __restrict__ r4 =
            reinterpret_cast<const float4*>(rep + (size_t)t * HH);

        float s0 = 0.f, s1 = 0.f, e0 = 0.f, e1 = 0.f;
#pragma unroll
        for (int it = 0; it < HH / 128; ++it) {
            const int idx = it * 32 + lane;
            const float4 r  = __ldcs(&r4[idx]);
            const float4 w0 = *reinterpret_cast<const float4*>(&s_w0[idx * 4]);
            const float4 w1 = *reinterpret_cast<const float4*>(&s_w1[idx * 4]);
            const float4 w2 = *reinterpret_cast<const float4*>(&s_w2[idx * 4]);
            const float4 w3 = *reinterpret_cast<const float4*>(&s_w3[idx * 4]);
            s0 += r.x * w0.x + r.y * w0.y + r.z * w0.z + r.w * w0.w;
            s1 += r.x * w1.x + r.y * w1.y + r.z * w1.z + r.w * w1.w;
            e0 += r.x * w2.x + r.y * w2.y + r.z * w2.z + r.w * w2.w;
            e1 += r.x * w3.x + r.y * w3.y + r.z * w3.z + r.w * w3.w;
        }
#pragma unroll
        for (int off = 16; off > 0; off >>= 1) {
            s0 += __shfl_down_sync(0xFFFFFFFFu, s0, off);
            s1 += __shfl_down_sync(0xFFFFFFFFu, s1, off);
            e0 += __shfl_down_sync(0xFFFFFFFFu, e0, off);
            e1 += __shfl_down_sync(0xFFFFFFFFu, e1, off);
        }
        if (lane == 0) {
            s0 += bs[0]; s1 += bs[1];
            e0 += be[0]; e1 += be[1];
            const bool m  = (mask[t] != 0);
            const bool sc = m && (s0 <= s1);
            const bool ec = m && (e0 <= e1);
            g_sS[t] = sc ? (s0 * Wm[0] + s1 * Wm[1]) : -1e30f;
            g_sE[t] = ec ? (e0 * Wm[2] + e1 * Wm[3]) : -1e30f;
            __threadfence();   // make this warp's score writes visible grid-wide
        }
        __syncthreads();
        if (threadIdx.x == 0) {
            atomicAdd(&g_ready[bid >> 8], 1);   // batch = bid / 256
        }
    }

    // ---------------- consumer part ----------------
    const long long tid = (long long)bid * 256 + threadIdx.x;
    const long long row = tid >> 9;          // b*S + i (512 threads per row)
    const int batch = (int)(row >> 11);      // row / 2048; uniform per block

    if (threadIdx.x == 0) {
        while (ld_acquire(&g_ready[batch]) < PROD_PER_BATCH) {
            __nanosleep(64);
        }
    }
    __syncthreads();

    const int j = (int)(tid & (SS / 4 - 1)) * 4;
    const int i = (int)(row & (SS - 1));

    const float sSv = g_sS[row];
    const long long ebase = row - i;         // b*S
    const float4 ev = *reinterpret_cast<const float4*>(&g_sE[ebase + j]);
    const float bmv = bm[0];

    float p0 = sSv + ev.x + bmv;
    float p1 = sSv + ev.y + bmv;
    float p2 = sSv + ev.z + bmv;
    float p3 = sSv + ev.w + bmv;

    const bool v0 = (i <= j + 0) && (p0 > 0.f);
    const bool v1 = (i <= j + 1) && (p1 > 0.f);
    const bool v2 = (i <= j + 2) && (p2 > 0.f);
    const bool v3 = (i <= j + 3) && (p3 > 0.f);

    float4 vo, so;
    vo.x = v0 ? 1.f : 0.f;  so.x = v0 ? p0 : 0.f;
    vo.y = v1 ? 1.f : 0.f;  so.y = v1 ? p1 : 0.f;
    vo.z = v2 ? 1.f : 0.f;  so.z = v2 ? p2 : 0.f;
    vo.w = v3 ? 1.f : 0.f;  so.w = v3 ? p3 : 0.f;

    const long long o = tid * 4;
    *reinterpret_cast<float4*>(out_valid + o) = vo;
    *reinterpret_cast<float4*>(out_score + o) = so;
}

extern "C" void kernel_launch(void* const* d_in, const int* in_sizes, int n_in,
                              void* d_out, int out_size)
{
    const float* rep  = (const float*)d_in[0];
    const int*   mask = (const int*)  d_in[1];
    const float* Ws   = (const float*)d_in[2];
    const float* bs   = (const float*)d_in[3];
    const float* We   = (const float*)d_in[4];
    const float* be   = (const float*)d_in[5];
    const float* Wm   = (const float*)d_in[6];
    const float* bm   = (const float*)d_in[7];

    float* out_valid = (float*)d_out;
    float* out_score = out_valid + BSS;

    static void* ready_addr = nullptr;
    if (ready_addr == nullptr) {
        cudaGetSymbolAddress(&ready_addr, g_ready);
    }
    // Reset per-batch flags (graph-capturable memset node).
    cudaMemsetAsync(ready_addr, 0, BB * sizeof(int));

    // Monolithic fused grid: 32768 blocks (same shape as the pair grid).
    const unsigned blocks = (unsigned)(BSS / 4 / 256);
    fused_kernel<<<blocks, 256>>>(rep, mask, Ws, bs, We, be, Wm, bm,
                                  out_valid, out_score);
}

// round 13
// speedup vs baseline: 1.0218x; 1.0218x over previous
#include <cuda_runtime.h>
#include <cuda_bf16.h>
#include <cstdint>

// Problem constants (fixed by reference setup_inputs)
#define BB 8
#define SS 2048
#define HH 1024
#define NTOK (BB * SS)                 // 16384
#define BSS ((long long)BB * SS * SS)  // 33,554,432

#define PROD_BLOCKS (NTOK / 8)         // 2048 producer blocks
#define PROD_PER_BATCH 256             // producer blocks per batch

// Scratch: per-token combined scores. Non-candidates encoded as -1e30 so that
// pair_score = sS + sE + bm is guaranteed <= 0 -> invalid -> outputs 0.
__device__ float g_sS[NTOK];
__device__ float g_sE[NTOK];
__device__ int   g_ready[BB];          // per-batch producer completion count

__device__ __forceinline__ int ld_acquire(const int* p) {
    int v;
    asm volatile("ld.global.acquire.gpu.b32 %0, [%1];" : "=r"(v) : "l"(p));
    return v;
}

// ---------------------------------------------------------------------------
// Fused kernel v2: no shared memory, full occupancy (8 blocks/SM).
// bid < PROD_BLOCKS: compute 8 token scores (one warp per token, weights
// via __ldg -> L1-broadcast), release per-batch flag.
// ALL blocks: acquire-wait on their batch's flag, then write their pair tile
// (R1 form: 4 el/thread, plain float4 stores, monolithic grid).
// ---------------------------------------------------------------------------
__global__ __launch_bounds__(256, 8) void fused_kernel(
    const float* __restrict__ rep,   // (B,S,H)
    const int*   __restrict__ mask,  // (B,S)
    const float* __restrict__ Ws,    // (H,2)
    const float* __restrict__ bs,    // (2,)
    const float* __restrict__ We,    // (H,2)
    const float* __restrict__ be,    // (2,)
    const float* __restrict__ Wm,    // (4,1)
    const float* __restrict__ bm,    // (1,)
    float* __restrict__ out_valid,
    float* __restrict__ out_score)
{
    const int bid = blockIdx.x;

    // ---------------- producer part ----------------
    if (bid < PROD_BLOCKS) {
        const int warp = threadIdx.x >> 5;
        const int lane = threadIdx.x & 31;
        const int t = bid * 8 + warp;

        const float4* __restrict__ r4 =
            reinterpret_cast<const float4*>(rep + (size_t)t * HH);
        const float4* __restrict__ Ws4 = reinterpret_cast<const float4*>(Ws);
        const float4* __restrict__ We4 = reinterpret_cast<const float4*>(We);

        float s0 = 0.f, s1 = 0.f, e0 = 0.f, e1 = 0.f;
#pragma unroll
        for (int it = 0; it < HH / 128; ++it) {
            const int idx = it * 32 + lane;
            const float4 r = __ldcs(&r4[idx]);
            // Ws rows 2h..2h+3 packed: float4 at index h/2 covers 2 h-values.
            // Load pairs (Ws[2h],Ws[2h+1]) for h = 4*idx .. 4*idx+3:
            const float4 wa = __ldg(&Ws4[idx * 2]);     // h=4idx, 4idx+1
            const float4 wb = __ldg(&Ws4[idx * 2 + 1]); // h=4idx+2, 4idx+3
            const float4 va = __ldg(&We4[idx * 2]);
            const float4 vb = __ldg(&We4[idx * 2 + 1]);
            // wa = (Ws0[h0], Ws1[h0], Ws0[h1], Ws1[h1]) etc.
            s0 += r.x * wa.x + r.y * wa.z + r.z * wb.x + r.w * wb.z;
            s1 += r.x * wa.y + r.y * wa.w + r.z * wb.y + r.w * wb.w;
            e0 += r.x * va.x + r.y * va.z + r.z * vb.x + r.w * vb.z;
            e1 += r.x * va.y + r.y * va.w + r.z * vb.y + r.w * vb.w;
        }
#pragma unroll
        for (int off = 16; off > 0; off >>= 1) {
            s0 += __shfl_down_sync(0xFFFFFFFFu, s0, off);
            s1 += __shfl_down_sync(0xFFFFFFFFu, s1, off);
            e0 += __shfl_down_sync(0xFFFFFFFFu, e0, off);
            e1 += __shfl_down_sync(0xFFFFFFFFu, e1, off);
        }
        if (lane == 0) {
            s0 += bs[0]; s1 += bs[1];
            e0 += be[0]; e1 += be[1];
            const bool m  = (mask[t] != 0);
            const bool sc = m && (s0 <= s1);
            const bool ec = m && (e0 <= e1);
            g_sS[t] = sc ? (s0 * Wm[0] + s1 * Wm[1]) : -1e30f;
            g_sE[t] = ec ? (e0 * Wm[2] + e1 * Wm[3]) : -1e30f;
            __threadfence();   // make score writes visible grid-wide
        }
        __syncthreads();
        if (threadIdx.x == 0) {
            atomicAdd(&g_ready[bid >> 8], 1);   // batch = bid / 256
        }
    }

    // ---------------- consumer part ----------------
    const long long tid = (long long)bid * 256 + threadIdx.x;
    const long long row = tid >> 9;          // b*S + i (512 threads per row)
    const int batch = (int)(row >> 11);      // row / 2048; uniform per block

    if (threadIdx.x == 0) {
        while (ld_acquire(&g_ready[batch]) < PROD_PER_BATCH) {
            __nanosleep(64);
        }
    }
    __syncthreads();

    const int j = (int)(tid & (SS / 4 - 1)) * 4;
    const int i = (int)(row & (SS - 1));

    const float sSv = g_sS[row];
    const long long ebase = row - i;         // b*S
    const float4 ev = *reinterpret_cast<const float4*>(&g_sE[ebase + j]);
    const float bmv = bm[0];

    float p0 = sSv + ev.x + bmv;
    float p1 = sSv + ev.y + bmv;
    float p2 = sSv + ev.z + bmv;
    float p3 = sSv + ev.w + bmv;

    const bool v0 = (i <= j + 0) && (p0 > 0.f);
    const bool v1 = (i <= j + 1) && (p1 > 0.f);
    const bool v2 = (i <= j + 2) && (p2 > 0.f);
    const bool v3 = (i <= j + 3) && (p3 > 0.f);

    float4 vo, so;
    vo.x = v0 ? 1.f : 0.f;  so.x = v0 ? p0 : 0.f;
    vo.y = v1 ? 1.f : 0.f;  so.y = v1 ? p1 : 0.f;
    vo.z = v2 ? 1.f : 0.f;  so.z = v2 ? p2 : 0.f;
    vo.w = v3 ? 1.f : 0.f;  so.w = v3 ? p3 : 0.f;

    const long long o = tid * 4;
    *reinterpret_cast<float4*>(out_valid + o) = vo;
    *reinterpret_cast<float4*>(out_score + o) = so;
}

extern "C" void kernel_launch(void* const* d_in, const int* in_sizes, int n_in,
                              void* d_out, int out_size)
{
    const float* rep  = (const float*)d_in[0];
    const int*   mask = (const int*)  d_in[1];
    const float* Ws   = (const float*)d_in[2];
    const float* bs   = (const float*)d_in[3];
    const float* We   = (const float*)d_in[4];
    const float* be   = (const float*)d_in[5];
    const float* Wm   = (const float*)d_in[6];
    const float* bm   = (const float*)d_in[7];

    float* out_valid = (float*)d_out;
    float* out_score = out_valid + BSS;

    static void* ready_addr = nullptr;
    if (ready_addr == nullptr) {
        cudaGetSymbolAddress(&ready_addr, g_ready);
    }
    // Reset per-batch flags (graph-capturable memset node).
    cudaMemsetAsync(ready_addr, 0, BB * sizeof(int));

    // Monolithic fused grid: 32768 blocks (same shape as the pair grid).
    const unsigned blocks = (unsigned)(BSS / 4 / 256);
    fused_kernel<<<blocks, 256>>>(rep, mask, Ws, bs, We, be, Wm, bm,
                                  out_valid, out_score);
}